// round 8
// baseline (speedup 1.0000x reference)
#include <cuda_runtime.h>
#include <cuda_bf16.h>
#include <cstdint>

// B=16, S=D=1024, M=16384. All operands: row-major bf16 hi/lo planes.
#define SL 16777216LL
#define M1 1048576LL

// slots (SL each): 0..11 converted inputs h/l; 12/13 qr, 14/15 qi, 16/17 kr,
// 18/19 ki, 20/21 vr, 22/23 vi; 24/25 krT, 26/27 vrT, 28/29 viT; 30/31 attn.
// weights at WB=32*SL: 12 x M1.
__device__ __align__(16) __nv_bfloat16 g_bf[32ULL * 16777216ULL + 12ULL * 1048576ULL];
// f32: 0 scores, SL out_r, 2*SL out_i
__device__ __align__(16) float g_f32[3ULL * 16777216ULL];

__device__ __forceinline__ uint32_t smem_u32(const void* p) {
    return (uint32_t)__cvta_generic_to_shared(p);
}
__device__ __forceinline__ void cp16(uint32_t d, const void* g) {
    asm volatile("cp.async.cg.shared.global [%0], [%1], 16;" :: "r"(d), "l"(g));
}
#define CP_COMMIT() asm volatile("cp.async.commit_group;" ::: "memory")

// swizzle for 64B-wide rows (off = row*64 + c16*16): XOR c16 bits with both
// row bit-pairs -> conflict-free ldmatrix phases.
__device__ __forceinline__ uint32_t sw64(uint32_t off) {
    return off ^ (((off >> 2) ^ (off >> 4)) & 0x30u);
}

#define LDSM4(r, a) asm volatile( \
    "ldmatrix.sync.aligned.m8n8.x4.shared.b16 {%0,%1,%2,%3}, [%4];" \
    : "=r"((r)[0]), "=r"((r)[1]), "=r"((r)[2]), "=r"((r)[3]) : "r"(a))

#define MMA16(d, a, b0, b1) asm volatile( \
    "mma.sync.aligned.m16n8k16.row.col.f32.bf16.bf16.f32 " \
    "{%0,%1,%2,%3}, {%4,%5,%6,%7}, {%8,%9}, {%0,%1,%2,%3};" \
    : "+f"((d)[0]), "+f"((d)[1]), "+f"((d)[2]), "+f"((d)[3]) \
    : "r"((a)[0]), "r"((a)[1]), "r"((a)[2]), "r"((a)[3]), "r"(b0), "r"(b1))

__device__ __forceinline__ void split_bf(float v, unsigned short& h, unsigned short& l) {
    __nv_bfloat16 bh = __float2bfloat16(v);
    h = __bfloat16_as_ushort(bh);
    l = __bfloat16_as_ushort(__float2bfloat16(v - __bfloat162float(bh)));
}
__device__ __forceinline__ uint32_t pack2(unsigned short a, unsigned short b) {
    return (uint32_t)a | ((uint32_t)b << 16);
}

// ---------------------------------------------------------------------------
// Split-bf16 HMMA GEMM, NT: C[m,n] = alpha * sum_k A[m,k]*B[n,k].
// A=Ah+Al, B=Bh+Bl: acc += Ah*Bh + Ah*Bl + Al*Bh.
// MODE 0: +bias[n], write bf16 hi/lo planes (coh,col_).
// MODE 1: *alpha, write f32 at g_f32+cf. npairs=2 accumulates second pair.
// Tiles: BM=BN=128, BK=32; 3-stage cp.async pipeline (32KB/stage, 96KB);
// 256 threads = 8 warps (2m x 4n), warp tile 64x32. 2 CTAs/SM.
// ---------------------------------------------------------------------------
template<int MODE>
__global__ __launch_bounds__(256, 2) void gemm_k(
    long long a1h, long long a1l, long long b1h, long long b1l,
    long long a2h, long long a2l, long long b2h, long long b2l,
    int npairs, const float* __restrict__ bias,
    long long coh, long long col_, long long cf,
    float alpha, long long sA, long long sB, long long sC)
{
    extern __shared__ __align__(128) char smem[];
    const uint32_t sbase = smem_u32(smem);

    const int tid = threadIdx.x;
    const int lane = tid & 31, wid = tid >> 5;
    const int wm = wid & 1, wn = wid >> 1;
    const int bm = blockIdx.y * 128, bn = blockIdx.x * 128;
    const long long bz = blockIdx.z;
    const long long azo = bz * sA, bzo = bz * sB, czo = bz * sC;

    float acc[4][4][4];
#pragma unroll
    for (int i = 0; i < 4; i++)
#pragma unroll
        for (int j = 0; j < 4; j++)
#pragma unroll
            for (int k = 0; k < 4; k++) acc[i][j][k] = 0.f;

    const int NCH = 32 * npairs;

    auto fill = [&](int c, int s) {
        const int p = c >> 5, kc = (c & 31) * 32;
        const long long Ah = (p ? a2h : a1h) + azo;
        const long long Al = (p ? a2l : a1l) + azo;
        const long long Bh = (p ? b2h : b1h) + bzo;
        const long long Bl = (p ? b2l : b1l) + bzo;
        const uint32_t stb = sbase + (uint32_t)s * 32768u;
#pragma unroll
        for (int i = 0; i < 2; i++) {
            const int u = tid + i * 256;
            const int r = u >> 2, cc = u & 3;
            const uint32_t off = sw64((uint32_t)(r * 64 + cc * 16));
            const long long ga = (long long)(bm + r) * 1024 + kc + cc * 8;
            const long long gb = (long long)(bn + r) * 1024 + kc + cc * 8;
            cp16(stb + off,           g_bf + Ah + ga);
            cp16(stb + 8192u + off,   g_bf + Al + ga);
            cp16(stb + 16384u + off,  g_bf + Bh + gb);
            cp16(stb + 24576u + off,  g_bf + Bl + gb);
        }
    };

    auto compute = [&](int s) {
        const uint32_t ab = sbase + (uint32_t)s * 32768u;
#pragma unroll
        for (int ks = 0; ks < 2; ks++) {
            const int c16 = ks * 2 + (lane >> 4);
            uint32_t ra[4][4], la[4][4];
#pragma unroll
            for (int ma = 0; ma < 4; ma++) {
                const int row = wm * 64 + ma * 16 + (lane & 15);
                const uint32_t off = sw64((uint32_t)(row * 64 + c16 * 16));
                LDSM4(ra[ma], ab + off);
                LDSM4(la[ma], ab + 8192u + off);
            }
            uint32_t rb[2][4], lb[2][4];
#pragma unroll
            for (int nb = 0; nb < 2; nb++) {
                const int row = wn * 32 + nb * 16 + (lane & 15);
                const uint32_t off = sw64((uint32_t)(row * 64 + c16 * 16));
                LDSM4(rb[nb], ab + 16384u + off);
                LDSM4(lb[nb], ab + 24576u + off);
            }
            // product-outermost: 16 distinct acc quads per pass
#pragma unroll
            for (int ma = 0; ma < 4; ma++)
#pragma unroll
                for (int nb = 0; nb < 2; nb++) {
                    MMA16(acc[ma][2 * nb],     ra[ma], rb[nb][0], rb[nb][2]);
                    MMA16(acc[ma][2 * nb + 1], ra[ma], rb[nb][1], rb[nb][3]);
                }
#pragma unroll
            for (int ma = 0; ma < 4; ma++)
#pragma unroll
                for (int nb = 0; nb < 2; nb++) {
                    MMA16(acc[ma][2 * nb],     ra[ma], lb[nb][0], lb[nb][2]);
                    MMA16(acc[ma][2 * nb + 1], ra[ma], lb[nb][1], lb[nb][3]);
                }
#pragma unroll
            for (int ma = 0; ma < 4; ma++)
#pragma unroll
                for (int nb = 0; nb < 2; nb++) {
                    MMA16(acc[ma][2 * nb],     la[ma], rb[nb][0], rb[nb][2]);
                    MMA16(acc[ma][2 * nb + 1], la[ma], rb[nb][1], rb[nb][3]);
                }
        }
    };

    fill(0, 0); CP_COMMIT();
    fill(1, 1); CP_COMMIT();
    for (int c = 0; c < NCH; c++) {
        asm volatile("cp.async.wait_group 1;" ::: "memory");
        __syncthreads();
        const int nx = c + 2;
        if (nx < NCH) fill(nx, nx % 3);
        CP_COMMIT();
        compute(c % 3);
    }

    // ---- epilogue ----
#pragma unroll
    for (int ma = 0; ma < 4; ma++) {
        const int r0 = bm + wm * 64 + ma * 16 + (lane >> 2);
#pragma unroll
        for (int na = 0; na < 4; na++) {
            const int cc = bn + wn * 32 + na * 8 + (lane & 3) * 2;
            float v0 = acc[ma][na][0], v1 = acc[ma][na][1];
            float v2 = acc[ma][na][2], v3 = acc[ma][na][3];
            if (MODE == 0) {
                const float b0 = bias[cc], b1 = bias[cc + 1];
                v0 += b0; v1 += b1; v2 += b0; v3 += b1;
                unsigned short h0, l0, h1, l1;
                split_bf(v0, h0, l0); split_bf(v1, h1, l1);
                *(uint32_t*)(g_bf + coh + (long long)r0 * 1024 + cc) = pack2(h0, h1);
                *(uint32_t*)(g_bf + col_ + (long long)r0 * 1024 + cc) = pack2(l0, l1);
                split_bf(v2, h0, l0); split_bf(v3, h1, l1);
                *(uint32_t*)(g_bf + coh + (long long)(r0 + 8) * 1024 + cc) = pack2(h0, h1);
                *(uint32_t*)(g_bf + col_ + (long long)(r0 + 8) * 1024 + cc) = pack2(l0, l1);
            } else {
                float2 w0 = make_float2(v0 * alpha, v1 * alpha);
                float2 w1 = make_float2(v2 * alpha, v3 * alpha);
                *(float2*)(g_f32 + cf + czo + (long long)r0 * 1024 + cc) = w0;
                *(float2*)(g_f32 + cf + czo + (long long)(r0 + 8) * 1024 + cc) = w1;
            }
        }
    }
}

// ---------------------------------------------------------------------------
// fp32 -> row-major bf16 hi/lo planes. 6 matrices in one launch (blockIdx.y).
// ---------------------------------------------------------------------------
__global__ __launch_bounds__(512) void conv_split6_k(
    const float* __restrict__ s0, const float* __restrict__ s1,
    const float* __restrict__ s2, const float* __restrict__ s3,
    const float* __restrict__ s4, const float* __restrict__ s5,
    long long dst0, long long dstride, int n8)
{
    const float* srcs[6] = {s0, s1, s2, s3, s4, s5};
    const float* src = srcs[blockIdx.y];
    const long long oh = dst0 + (long long)blockIdx.y * 2 * dstride;
    const long long ol = oh + dstride;
    for (int t = blockIdx.x * 512 + threadIdx.x; t < n8; t += gridDim.x * 512) {
        const float4* s4p = (const float4*)(src + (long long)t * 8);
        float4 v0 = s4p[0], v1 = s4p[1];
        float vv[8] = {v0.x, v0.y, v0.z, v0.w, v1.x, v1.y, v1.z, v1.w};
        unsigned short hs[8], ls[8];
#pragma unroll
        for (int e = 0; e < 8; e++) split_bf(vv[e], hs[e], ls[e]);
        *(uint4*)(g_bf + oh + (long long)t * 8) = *(uint4*)hs;
        *(uint4*)(g_bf + ol + (long long)t * 8) = *(uint4*)ls;
    }
}

// ---------------------------------------------------------------------------
// Batched (16x) 1024x1024 transpose of bf16 hi/lo planes. 32x32 tiles.
// ---------------------------------------------------------------------------
__global__ __launch_bounds__(256) void transpose_k(
    long long sh_, long long sl_, long long dh_, long long dl_)
{
    __shared__ unsigned short th[32][33], tl[32][33];
    const long long b = (long long)blockIdx.z << 20;
    const int tx = threadIdx.x & 31, ty = threadIdx.x >> 5;
    const int x0 = blockIdx.x * 32, y0 = blockIdx.y * 32;
    const unsigned short* sh = (const unsigned short*)(g_bf + sh_ + b);
    const unsigned short* sl = (const unsigned short*)(g_bf + sl_ + b);
    unsigned short* dh = (unsigned short*)(g_bf + dh_ + b);
    unsigned short* dl = (unsigned short*)(g_bf + dl_ + b);
#pragma unroll
    for (int j = 0; j < 4; j++) {
        const int r = y0 + ty + 8 * j;
        th[ty + 8 * j][tx] = sh[(long long)r * 1024 + x0 + tx];
        tl[ty + 8 * j][tx] = sl[(long long)r * 1024 + x0 + tx];
    }
    __syncthreads();
#pragma unroll
    for (int j = 0; j < 4; j++) {
        const int r = x0 + ty + 8 * j;
        dh[(long long)r * 1024 + y0 + tx] = th[tx][ty + 8 * j];
        dl[(long long)r * 1024 + y0 + tx] = tl[tx][ty + 8 * j];
    }
}

// ---------------------------------------------------------------------------
// Row softmax over fp32 scores -> attn bf16 hi/lo planes.
// ---------------------------------------------------------------------------
__global__ __launch_bounds__(256) void softmax_k(long long attnH, long long attnL)
{
    __shared__ float red[8];
    const int tid = threadIdx.x;
    const long long row = blockIdx.x;
    const float* r = g_f32 + row * 1024;

    float4 v = ((const float4*)r)[tid];
    float m = fmaxf(fmaxf(v.x, v.y), fmaxf(v.z, v.w));
#pragma unroll
    for (int o = 16; o; o >>= 1) m = fmaxf(m, __shfl_xor_sync(0xffffffffu, m, o));
    if ((tid & 31) == 0) red[tid >> 5] = m;
    __syncthreads();
    float bm = red[0];
#pragma unroll
    for (int i = 1; i < 8; i++) bm = fmaxf(bm, red[i]);
    __syncthreads();

    v.x = __expf(v.x - bm); v.y = __expf(v.y - bm);
    v.z = __expf(v.z - bm); v.w = __expf(v.w - bm);
    float s = v.x + v.y + v.z + v.w;
#pragma unroll
    for (int o = 16; o; o >>= 1) s += __shfl_xor_sync(0xffffffffu, s, o);
    if ((tid & 31) == 0) red[tid >> 5] = s;
    __syncthreads();
    float bs = 0.f;
#pragma unroll
    for (int i = 0; i < 8; i++) bs += red[i];
    const float inv = 1.0f / bs;
    v.x *= inv; v.y *= inv; v.z *= inv; v.w *= inv;

    unsigned short h[4], l[4];
    split_bf(v.x, h[0], l[0]); split_bf(v.y, h[1], l[1]);
    split_bf(v.z, h[2], l[2]); split_bf(v.w, h[3], l[3]);
    uint2 ph = make_uint2(pack2(h[0], h[1]), pack2(h[2], h[3]));
    uint2 pl = make_uint2(pack2(l[0], l[1]), pack2(l[2], l[3]));
    *(uint2*)(g_bf + attnH + row * 1024 + tid * 4) = ph;
    *(uint2*)(g_bf + attnL + row * 1024 + tid * 4) = pl;
}

// ---------------------------------------------------------------------------
// Complex LayerNorm -> d_out [2,B,S,D].
// ---------------------------------------------------------------------------
__global__ __launch_bounds__(256) void complex_ln_k(
    long long offR, long long offI,
    const float* __restrict__ a2, const float* __restrict__ b2,
    float* __restrict__ out)
{
    __shared__ float redA[8], redB[8];
    const long long row = blockIdx.x;
    const int tid = threadIdx.x;

    float4 zr = ((const float4*)(g_f32 + offR + row * 1024))[tid];
    float4 zi = ((const float4*)(g_f32 + offI + row * 1024))[tid];

    float sr = zr.x + zr.y + zr.z + zr.w;
    float si = zi.x + zi.y + zi.z + zi.w;
#pragma unroll
    for (int o = 16; o; o >>= 1) {
        sr += __shfl_xor_sync(0xffffffffu, sr, o);
        si += __shfl_xor_sync(0xffffffffu, si, o);
    }
    if ((tid & 31) == 0) { redA[tid >> 5] = sr; redB[tid >> 5] = si; }
    __syncthreads();
    float mr = 0.f, mi = 0.f;
#pragma unroll
    for (int i = 0; i < 8; i++) { mr += redA[i]; mi += redB[i]; }
    mr *= (1.f / 1024.f); mi *= (1.f / 1024.f);

    zr.x -= mr; zr.y -= mr; zr.z -= mr; zr.w -= mr;
    zi.x -= mi; zi.y -= mi; zi.z -= mi; zi.w -= mi;

    float vr = (zr.x * zr.x - zi.x * zi.x) + (zr.y * zr.y - zi.y * zi.y)
             + (zr.z * zr.z - zi.z * zi.z) + (zr.w * zr.w - zi.w * zi.w);
    float vi = 2.f * (zr.x * zi.x + zr.y * zi.y + zr.z * zi.z + zr.w * zi.w);
    __syncthreads();
#pragma unroll
    for (int o = 16; o; o >>= 1) {
        vr += __shfl_xor_sync(0xffffffffu, vr, o);
        vi += __shfl_xor_sync(0xffffffffu, vi, o);
    }
    if ((tid & 31) == 0) { redA[tid >> 5] = vr; redB[tid >> 5] = vi; }
    __syncthreads();
    float cr = 0.f, ci = 0.f;
#pragma unroll
    for (int i = 0; i < 8; i++) { cr += redA[i]; ci += redB[i]; }
    cr = cr * (1.f / 1024.f) + 1e-6f;
    ci = ci * (1.f / 1024.f);

    const float rmod = sqrtf(cr * cr + ci * ci);
    const float ssr = sqrtf(fmaxf(0.5f * (rmod + cr), 0.f));
    const float ssi = copysignf(sqrtf(fmaxf(0.5f * (rmod - cr), 0.f)), ci);
    const float inv = 1.f / rmod;

    float4 a4 = ((const float4*)a2)[tid];
    float4 b4 = ((const float4*)b2)[tid];

    float4 yr, yi;
    yr.x = (zr.x * ssr + zi.x * ssi) * inv;  yi.x = (zi.x * ssr - zr.x * ssi) * inv;
    yr.y = (zr.y * ssr + zi.y * ssi) * inv;  yi.y = (zi.y * ssr - zr.y * ssi) * inv;
    yr.z = (zr.z * ssr + zi.z * ssi) * inv;  yi.z = (zi.z * ssr - zr.z * ssi) * inv;
    yr.w = (zr.w * ssr + zi.w * ssi) * inv;  yi.w = (zi.w * ssr - zr.w * ssi) * inv;

    yr.x = a4.x * yr.x + b4.x;  yi.x = a4.x * yi.x;
    yr.y = a4.y * yr.y + b4.y;  yi.y = a4.y * yi.y;
    yr.z = a4.z * yr.z + b4.z;  yi.z = a4.z * yi.z;
    yr.w = a4.w * yr.w + b4.w;  yi.w = a4.w * yi.w;

    ((float4*)(out + row * 1024))[tid] = yr;
    ((float4*)(out + 16777216LL + row * 1024))[tid] = yi;
}

// ---------------------------------------------------------------------------
extern "C" void kernel_launch(void* const* d_in, const int* in_sizes, int n_in,
                              void* d_out, int out_size)
{
    const float* a2 = (const float*)d_in[18];
    const float* b2 = (const float*)d_in[19];
    float* out = (float*)d_out;
    const float* Bv[6] = {(const float*)d_in[7], (const float*)d_in[9], (const float*)d_in[11],
                          (const float*)d_in[13], (const float*)d_in[15], (const float*)d_in[17]};

    const int SMEM = 98304;
    cudaFuncSetAttribute(gemm_k<0>, cudaFuncAttributeMaxDynamicSharedMemorySize, SMEM);
    cudaFuncSetAttribute(gemm_k<1>, cudaFuncAttributeMaxDynamicSharedMemorySize, SMEM);

    const long long WB = 32 * SL;

    // launch 0: all 6 input converts -> slots 0..11
    conv_split6_k<<<dim3(2048, 6), 512>>>(
        (const float*)d_in[0], (const float*)d_in[1], (const float*)d_in[2],
        (const float*)d_in[3], (const float*)d_in[4], (const float*)d_in[5],
        0, SL, 2097152);
    // launch 1: all 6 weight converts -> WB...
    conv_split6_k<<<dim3(256, 6), 512>>>(
        (const float*)d_in[6], (const float*)d_in[8], (const float*)d_in[10],
        (const float*)d_in[12], (const float*)d_in[14], (const float*)d_in[16],
        WB, M1, 131072);

    dim3 blk(256);
    dim3 gp(8, 128, 1);
    // launches 2..7: projections -> slots 12..23 (launch 5 = ncu capture)
    for (int i = 0; i < 6; i++)
        gemm_k<0><<<gp, blk, SMEM>>>(
            (2 * i) * SL, (2 * i + 1) * SL, WB + 2 * i * M1, WB + (2 * i + 1) * M1,
            0, 0, 0, 0, 1, Bv[i],
            (12 + 2 * i) * SL, (13 + 2 * i) * SL, 0, 1.f, 0, 0, 0);

    // transposes: kr(16,17)->krT(24,25), vr(20,21)->vrT(26,27), vi(22,23)->viT(28,29)
    dim3 gt(32, 32, 16);
    transpose_k<<<gt, 256>>>(16 * SL, 17 * SL, 24 * SL, 25 * SL);
    transpose_k<<<gt, 256>>>(20 * SL, 21 * SL, 26 * SL, 27 * SL);
    transpose_k<<<gt, 256>>>(22 * SL, 23 * SL, 28 * SL, 29 * SL);

    // scores = 0.125*(qr@krT^T + qi@ki^T) -> g_f32[0]
    dim3 gb(8, 8, 16);
    gemm_k<1><<<gb, blk, SMEM>>>(
        12 * SL, 13 * SL, 24 * SL, 25 * SL,
        14 * SL, 15 * SL, 18 * SL, 19 * SL,
        2, nullptr, 0, 0, 0, 0.125f, M1, M1, M1);

    // softmax -> attn (30,31)
    softmax_k<<<16384, 256>>>(30 * SL, 31 * SL);

    // out_r = attn@vrT^T -> g_f32[SL]; out_i = attn@viT^T -> g_f32[2SL]
    gemm_k<1><<<gb, blk, SMEM>>>(
        30 * SL, 31 * SL, 26 * SL, 27 * SL,
        0, 0, 0, 0, 1, nullptr, 0, 0, SL, 1.f, M1, M1, M1);
    gemm_k<1><<<gb, blk, SMEM>>>(
        30 * SL, 31 * SL, 28 * SL, 29 * SL,
        0, 0, 0, 0, 1, nullptr, 0, 0, 2 * SL, 1.f, M1, M1, M1);

    // complex layernorm -> d_out
    complex_ln_k<<<16384, 256>>>(SL, 2 * SL, a2, b2, out);
}

// round 12
// speedup vs baseline: 1.0106x; 1.0106x over previous
#include <cuda_runtime.h>
#include <cuda_fp16.h>
#include <cstdint>

// B=16, S=D=1024, M=16384. All operands: row-major fp16 hi/lo planes.
#define SL 16777216LL
#define M1 1048576LL

// slots (SL each): 0..11 converted inputs h/l; 12/13 qr, 14/15 qi, 16/17 kr,
// 18/19 ki, 20/21 vr, 22/23 vi; 24/25 krT, 26/27 vrT, 28/29 viT; 30/31 attn.
// weights at WB=32*SL: 12 x M1.
__device__ __align__(16) unsigned short g_hf[32ULL * 16777216ULL + 12ULL * 1048576ULL];
// f32: 0 scores, SL out_r, 2*SL out_i
__device__ __align__(16) float g_f32[3ULL * 16777216ULL];

__device__ __forceinline__ uint32_t smem_u32(const void* p) {
    return (uint32_t)__cvta_generic_to_shared(p);
}
__device__ __forceinline__ void cp16(uint32_t d, const void* g) {
    asm volatile("cp.async.cg.shared.global [%0], [%1], 16;" :: "r"(d), "l"(g));
}
#define CP_COMMIT() asm volatile("cp.async.commit_group;" ::: "memory")

#define LDSM4(r, a) asm volatile( \
    "ldmatrix.sync.aligned.m8n8.x4.shared.b16 {%0,%1,%2,%3}, [%4];" \
    : "=r"((r)[0]), "=r"((r)[1]), "=r"((r)[2]), "=r"((r)[3]) : "r"(a))

// f16 x f16 -> f32 accum
#define MMAF(d, a, b0, b1) asm volatile( \
    "mma.sync.aligned.m16n8k16.row.col.f32.f16.f16.f32 " \
    "{%0,%1,%2,%3}, {%4,%5,%6,%7}, {%8,%9}, {%0,%1,%2,%3};" \
    : "+f"((d)[0]), "+f"((d)[1]), "+f"((d)[2]), "+f"((d)[3]) \
    : "r"((a)[0]), "r"((a)[1]), "r"((a)[2]), "r"((a)[3]), "r"(b0), "r"(b1))

// f16 x f16 -> f16 accum (2 packed regs)
#define MMAH(d, a, b0, b1) asm volatile( \
    "mma.sync.aligned.m16n8k16.row.col.f16.f16.f16.f16 " \
    "{%0,%1}, {%2,%3,%4,%5}, {%6,%7}, {%0,%1};" \
    : "+r"((d)[0]), "+r"((d)[1]) \
    : "r"((a)[0]), "r"((a)[1]), "r"((a)[2]), "r"((a)[3]), "r"(b0), "r"(b1))

__device__ __forceinline__ void split_h(float v, unsigned short& h, unsigned short& l) {
    __half hh = __float2half_rn(v);
    h = __half_as_ushort(hh);
    l = __half_as_ushort(__float2half_rn(v - __half2float(hh)));
}
__device__ __forceinline__ uint32_t pack2(unsigned short a, unsigned short b) {
    return (uint32_t)a | ((uint32_t)b << 16);
}

// ---------------------------------------------------------------------------
// Split-fp16 HMMA GEMM, NT: C[m,n] = alpha * sum_k A[m,k]*B[n,k].
// A=Ah+Al, B=Bh+Bl. hh -> f32 accum; (hl + lh) -> shared f16 accum (2x-rate
// path); ll dropped (~2^-22). Epilogue merges accumulators.
// MODE 0: +bias[n], write fp16 hi/lo planes. MODE 1: *alpha -> f32.
// Tiles: BM=BN=128, BK=64; 3-stage cp.async; SW128 swizzle; 512 thr,
// 16 warps (4m x 4n), warp tile 32x32.
// ---------------------------------------------------------------------------
template<int MODE>
__global__ __launch_bounds__(512, 1) void gemm_k(
    long long a1h, long long a1l, long long b1h, long long b1l,
    long long a2h, long long a2l, long long b2h, long long b2l,
    int npairs, const float* __restrict__ bias,
    long long coh, long long col_, long long cf,
    float alpha, long long sA, long long sB, long long sC)
{
    extern __shared__ __align__(128) char smem[];
    const uint32_t sbase = smem_u32(smem);

    const int tid = threadIdx.x;
    const int lane = tid & 31, wid = tid >> 5;
    const int wm = wid & 3, wn = wid >> 2;
    const int bm = blockIdx.y * 128, bn = blockIdx.x * 128;
    const long long bz = blockIdx.z;
    const long long azo = bz * sA, bzo = bz * sB, czo = bz * sC;

    float acc[2][4][4];
    uint32_t facc[2][4][2];
#pragma unroll
    for (int i = 0; i < 2; i++)
#pragma unroll
        for (int j = 0; j < 4; j++) {
#pragma unroll
            for (int k = 0; k < 4; k++) acc[i][j][k] = 0.f;
            facc[i][j][0] = 0u; facc[i][j][1] = 0u;
        }

    const int NCH = 16 * npairs;
    const int fr = tid >> 3, fc = tid & 7;

    auto fill = [&](int c, int s) {
        const int p = c >> 4, kc = (c & 15) * 64;
        const long long Ah = (p ? a2h : a1h) + azo;
        const long long Al = (p ? a2l : a1l) + azo;
        const long long Bh = (p ? b2h : b1h) + bzo;
        const long long Bl = (p ? b2l : b1l) + bzo;
        const uint32_t stb = sbase + (uint32_t)s * 65536u;
#pragma unroll
        for (int i = 0; i < 2; i++) {
            const int r = fr + i * 64;
            uint32_t off = (uint32_t)(r * 128 + fc * 16);
            off ^= (off >> 3) & 0x70u;
            const long long ga = (long long)(bm + r) * 1024 + kc + fc * 8;
            const long long gb = (long long)(bn + r) * 1024 + kc + fc * 8;
            cp16(stb + off,           g_hf + Ah + ga);
            cp16(stb + 16384u + off,  g_hf + Al + ga);
            cp16(stb + 32768u + off,  g_hf + Bh + gb);
            cp16(stb + 49152u + off,  g_hf + Bl + gb);
        }
    };

    auto compute = [&](int s) {
        const uint32_t ab = sbase + (uint32_t)s * 65536u;
        const uint32_t bhb = ab + 32768u;
#pragma unroll
        for (int ks = 0; ks < 4; ks++) {
            const int c16 = ks * 2 + (lane >> 4);
            uint32_t ra[2][4], la[2][4];
#pragma unroll
            for (int ma = 0; ma < 2; ma++) {
                const int row = wm * 32 + ma * 16 + (lane & 15);
                uint32_t off = (uint32_t)(row * 128 + c16 * 16);
                off ^= (off >> 3) & 0x70u;
                LDSM4(ra[ma], ab + off);
                LDSM4(la[ma], ab + 16384u + off);
            }
            uint32_t rb[2][4], lb[2][4];
#pragma unroll
            for (int nb = 0; nb < 2; nb++) {
                const int row = wn * 32 + nb * 16 + (lane & 15);
                uint32_t off = (uint32_t)(row * 128 + c16 * 16);
                off ^= (off >> 3) & 0x70u;
                LDSM4(rb[nb], bhb + off);
                LDSM4(lb[nb], bhb + 16384u + off);
            }
            // pass 1: hh -> f32 acc (8 distinct quads)
#pragma unroll
            for (int ma = 0; ma < 2; ma++)
#pragma unroll
                for (int nb = 0; nb < 2; nb++) {
                    MMAF(acc[ma][2 * nb],     ra[ma], rb[nb][0], rb[nb][2]);
                    MMAF(acc[ma][2 * nb + 1], ra[ma], rb[nb][1], rb[nb][3]);
                }
            // pass 2: hl -> f16 acc (8 distinct quads)
#pragma unroll
            for (int ma = 0; ma < 2; ma++)
#pragma unroll
                for (int nb = 0; nb < 2; nb++) {
                    MMAH(facc[ma][2 * nb],     ra[ma], lb[nb][0], lb[nb][2]);
                    MMAH(facc[ma][2 * nb + 1], ra[ma], lb[nb][1], lb[nb][3]);
                }
            // pass 3: lh -> f16 acc
#pragma unroll
            for (int ma = 0; ma < 2; ma++)
#pragma unroll
                for (int nb = 0; nb < 2; nb++) {
                    MMAH(facc[ma][2 * nb],     la[ma], rb[nb][0], rb[nb][2]);
                    MMAH(facc[ma][2 * nb + 1], la[ma], rb[nb][1], rb[nb][3]);
                }
        }
    };

    fill(0, 0); CP_COMMIT();
    fill(1, 1); CP_COMMIT();
    for (int c = 0; c < NCH; c++) {
        asm volatile("cp.async.wait_group 1;" ::: "memory");
        __syncthreads();
        const int nx = c + 2;
        if (nx < NCH) fill(nx, nx % 3);
        CP_COMMIT();
        compute(c % 3);
    }

    // ---- epilogue: merge f16 cross accumulators, then store ----
#pragma unroll
    for (int ma = 0; ma < 2; ma++) {
        const int r0 = bm + wm * 32 + ma * 16 + (lane >> 2);
#pragma unroll
        for (int na = 0; na < 4; na++) {
            const int cc = bn + wn * 32 + na * 8 + (lane & 3) * 2;
            __half2 x0 = *reinterpret_cast<__half2*>(&facc[ma][na][0]);
            __half2 x1 = *reinterpret_cast<__half2*>(&facc[ma][na][1]);
            float v0 = acc[ma][na][0] + __low2float(x0);
            float v1 = acc[ma][na][1] + __high2float(x0);
            float v2 = acc[ma][na][2] + __low2float(x1);
            float v3 = acc[ma][na][3] + __high2float(x1);
            if (MODE == 0) {
                const float b0 = bias[cc], b1 = bias[cc + 1];
                v0 += b0; v1 += b1; v2 += b0; v3 += b1;
                unsigned short h0, l0, h1, l1;
                split_h(v0, h0, l0); split_h(v1, h1, l1);
                *(uint32_t*)(g_hf + coh + (long long)r0 * 1024 + cc) = pack2(h0, h1);
                *(uint32_t*)(g_hf + col_ + (long long)r0 * 1024 + cc) = pack2(l0, l1);
                split_h(v2, h0, l0); split_h(v3, h1, l1);
                *(uint32_t*)(g_hf + coh + (long long)(r0 + 8) * 1024 + cc) = pack2(h0, h1);
                *(uint32_t*)(g_hf + col_ + (long long)(r0 + 8) * 1024 + cc) = pack2(l0, l1);
            } else {
                float2 w0 = make_float2(v0 * alpha, v1 * alpha);
                float2 w1 = make_float2(v2 * alpha, v3 * alpha);
                *(float2*)(g_f32 + cf + czo + (long long)r0 * 1024 + cc) = w0;
                *(float2*)(g_f32 + cf + czo + (long long)(r0 + 8) * 1024 + cc) = w1;
            }
        }
    }
}

// ---------------------------------------------------------------------------
// fp32 -> row-major fp16 hi/lo planes. 6 matrices in one launch (blockIdx.y).
// ---------------------------------------------------------------------------
__global__ __launch_bounds__(512) void conv_split6_k(
    const float* __restrict__ s0, const float* __restrict__ s1,
    const float* __restrict__ s2, const float* __restrict__ s3,
    const float* __restrict__ s4, const float* __restrict__ s5,
    long long dst0, long long dstride, int n8)
{
    const float* srcs[6] = {s0, s1, s2, s3, s4, s5};
    const float* src = srcs[blockIdx.y];
    const long long oh = dst0 + (long long)blockIdx.y * 2 * dstride;
    const long long ol = oh + dstride;
    for (int t = blockIdx.x * 512 + threadIdx.x; t < n8; t += gridDim.x * 512) {
        const float4* s4p = (const float4*)(src + (long long)t * 8);
        float4 v0 = s4p[0], v1 = s4p[1];
        float vv[8] = {v0.x, v0.y, v0.z, v0.w, v1.x, v1.y, v1.z, v1.w};
        unsigned short hs[8], ls[8];
#pragma unroll
        for (int e = 0; e < 8; e++) split_h(vv[e], hs[e], ls[e]);
        *(uint4*)(g_hf + oh + (long long)t * 8) = *(uint4*)hs;
        *(uint4*)(g_hf + ol + (long long)t * 8) = *(uint4*)ls;
    }
}

// ---------------------------------------------------------------------------
// Batched (16x) 1024x1024 transpose of fp16 hi/lo planes. 32x32 tiles.
// ---------------------------------------------------------------------------
__global__ __launch_bounds__(256) void transpose_k(
    long long sh_, long long sl_, long long dh_, long long dl_)
{
    __shared__ unsigned short th[32][33], tl[32][33];
    const long long b = (long long)blockIdx.z << 20;
    const int tx = threadIdx.x & 31, ty = threadIdx.x >> 5;
    const int x0 = blockIdx.x * 32, y0 = blockIdx.y * 32;
    const unsigned short* sh = g_hf + sh_ + b;
    const unsigned short* sl = g_hf + sl_ + b;
    unsigned short* dh = g_hf + dh_ + b;
    unsigned short* dl = g_hf + dl_ + b;
#pragma unroll
    for (int j = 0; j < 4; j++) {
        const int r = y0 + ty + 8 * j;
        th[ty + 8 * j][tx] = sh[(long long)r * 1024 + x0 + tx];
        tl[ty + 8 * j][tx] = sl[(long long)r * 1024 + x0 + tx];
    }
    __syncthreads();
#pragma unroll
    for (int j = 0; j < 4; j++) {
        const int r = x0 + ty + 8 * j;
        dh[(long long)r * 1024 + y0 + tx] = th[tx][ty + 8 * j];
        dl[(long long)r * 1024 + y0 + tx] = tl[tx][ty + 8 * j];
    }
}

// ---------------------------------------------------------------------------
// Row softmax over fp32 scores -> attn fp16 hi/lo planes.
// ---------------------------------------------------------------------------
__global__ __launch_bounds__(256) void softmax_k(long long attnH, long long attnL)
{
    __shared__ float red[8];
    const int tid = threadIdx.x;
    const long long row = blockIdx.x;
    const float* r = g_f32 + row * 1024;

    float4 v = ((const float4*)r)[tid];
    float m = fmaxf(fmaxf(v.x, v.y), fmaxf(v.z, v.w));
#pragma unroll
    for (int o = 16; o; o >>= 1) m = fmaxf(m, __shfl_xor_sync(0xffffffffu, m, o));
    if ((tid & 31) == 0) red[tid >> 5] = m;
    __syncthreads();
    float bm = red[0];
#pragma unroll
    for (int i = 1; i < 8; i++) bm = fmaxf(bm, red[i]);
    __syncthreads();

    v.x = __expf(v.x - bm); v.y = __expf(v.y - bm);
    v.z = __expf(v.z - bm); v.w = __expf(v.w - bm);
    float s = v.x + v.y + v.z + v.w;
#pragma unroll
    for (int o = 16; o; o >>= 1) s += __shfl_xor_sync(0xffffffffu, s, o);
    if ((tid & 31) == 0) red[tid >> 5] = s;
    __syncthreads();
    float bs = 0.f;
#pragma unroll
    for (int i = 0; i < 8; i++) bs += red[i];
    const float inv = 1.0f / bs;
    v.x *= inv; v.y *= inv; v.z *= inv; v.w *= inv;

    unsigned short h[4], l[4];
    split_h(v.x, h[0], l[0]); split_h(v.y, h[1], l[1]);
    split_h(v.z, h[2], l[2]); split_h(v.w, h[3], l[3]);
    uint2 ph = make_uint2(pack2(h[0], h[1]), pack2(h[2], h[3]));
    uint2 pl = make_uint2(pack2(l[0], l[1]), pack2(l[2], l[3]));
    *(uint2*)(g_hf + attnH + row * 1024 + tid * 4) = ph;
    *(uint2*)(g_hf + attnL + row * 1024 + tid * 4) = pl;
}

// ---------------------------------------------------------------------------
// Complex LayerNorm -> d_out [2,B,S,D].
// ---------------------------------------------------------------------------
__global__ __launch_bounds__(256) void complex_ln_k(
    long long offR, long long offI,
    const float* __restrict__ a2, const float* __restrict__ b2,
    float* __restrict__ out)
{
    __shared__ float redA[8], redB[8];
    const long long row = blockIdx.x;
    const int tid = threadIdx.x;

    float4 zr = ((const float4*)(g_f32 + offR + row * 1024))[tid];
    float4 zi = ((const float4*)(g_f32 + offI + row * 1024))[tid];

    float sr = zr.x + zr.y + zr.z + zr.w;
    float si = zi.x + zi.y + zi.z + zi.w;
#pragma unroll
    for (int o = 16; o; o >>= 1) {
        sr += __shfl_xor_sync(0xffffffffu, sr, o);
        si += __shfl_xor_sync(0xffffffffu, si, o);
    }
    if ((tid & 31) == 0) { redA[tid >> 5] = sr; redB[tid >> 5] = si; }
    __syncthreads();
    float mr = 0.f, mi = 0.f;
#pragma unroll
    for (int i = 0; i < 8; i++) { mr += redA[i]; mi += redB[i]; }
    mr *= (1.f / 1024.f); mi *= (1.f / 1024.f);

    zr.x -= mr; zr.y -= mr; zr.z -= mr; zr.w -= mr;
    zi.x -= mi; zi.y -= mi; zi.z -= mi; zi.w -= mi;

    float vr = (zr.x * zr.x - zi.x * zi.x) + (zr.y * zr.y - zi.y * zi.y)
             + (zr.z * zr.z - zi.z * zi.z) + (zr.w * zr.w - zi.w * zi.w);
    float vi = 2.f * (zr.x * zi.x + zr.y * zi.y + zr.z * zi.z + zr.w * zi.w);
    __syncthreads();
#pragma unroll
    for (int o = 16; o; o >>= 1) {
        vr += __shfl_xor_sync(0xffffffffu, vr, o);
        vi += __shfl_xor_sync(0xffffffffu, vi, o);
    }
    if ((tid & 31) == 0) { redA[tid >> 5] = vr; redB[tid >> 5] = vi; }
    __syncthreads();
    float cr = 0.f, ci = 0.f;
#pragma unroll
    for (int i = 0; i < 8; i++) { cr += redA[i]; ci += redB[i]; }
    cr = cr * (1.f / 1024.f) + 1e-6f;
    ci = ci * (1.f / 1024.f);

    const float rmod = sqrtf(cr * cr + ci * ci);
    const float ssr = sqrtf(fmaxf(0.5f * (rmod + cr), 0.f));
    const float ssi = copysignf(sqrtf(fmaxf(0.5f * (rmod - cr), 0.f)), ci);
    const float inv = 1.f / rmod;

    float4 a4 = ((const float4*)a2)[tid];
    float4 b4 = ((const float4*)b2)[tid];

    float4 yr, yi;
    yr.x = (zr.x * ssr + zi.x * ssi) * inv;  yi.x = (zi.x * ssr - zr.x * ssi) * inv;
    yr.y = (zr.y * ssr + zi.y * ssi) * inv;  yi.y = (zi.y * ssr - zr.y * ssi) * inv;
    yr.z = (zr.z * ssr + zi.z * ssi) * inv;  yi.z = (zi.z * ssr - zr.z * ssi) * inv;
    yr.w = (zr.w * ssr + zi.w * ssi) * inv;  yi.w = (zi.w * ssr - zr.w * ssi) * inv;

    yr.x = a4.x * yr.x + b4.x;  yi.x = a4.x * yi.x;
    yr.y = a4.y * yr.y + b4.y;  yi.y = a4.y * yi.y;
    yr.z = a4.z * yr.z + b4.z;  yi.z = a4.z * yi.z;
    yr.w = a4.w * yr.w + b4.w;  yi.w = a4.w * yi.w;

    ((float4*)(out + row * 1024))[tid] = yr;
    ((float4*)(out + 16777216LL + row * 1024))[tid] = yi;
}

// ---------------------------------------------------------------------------
extern "C" void kernel_launch(void* const* d_in, const int* in_sizes, int n_in,
                              void* d_out, int out_size)
{
    const float* a2 = (const float*)d_in[18];
    const float* b2 = (const float*)d_in[19];
    float* out = (float*)d_out;
    const float* Bv[6] = {(const float*)d_in[7], (const float*)d_in[9], (const float*)d_in[11],
                          (const float*)d_in[13], (const float*)d_in[15], (const float*)d_in[17]};

    const int SMEM = 196608;
    cudaFuncSetAttribute(gemm_k<0>, cudaFuncAttributeMaxDynamicSharedMemorySize, SMEM);
    cudaFuncSetAttribute(gemm_k<1>, cudaFuncAttributeMaxDynamicSharedMemorySize, SMEM);

    const long long WB = 32 * SL;

    // launch 0: all 6 input converts -> slots 0..11
    conv_split6_k<<<dim3(2048, 6), 512>>>(
        (const float*)d_in[0], (const float*)d_in[1], (const float*)d_in[2],
        (const float*)d_in[3], (const float*)d_in[4], (const float*)d_in[5],
        0, SL, 2097152);
    // launch 1: all 6 weight converts -> WB...
    conv_split6_k<<<dim3(256, 6), 512>>>(
        (const float*)d_in[6], (const float*)d_in[8], (const float*)d_in[10],
        (const float*)d_in[12], (const float*)d_in[14], (const float*)d_in[16],
        WB, M1, 131072);

    dim3 blk(512);
    dim3 gp(8, 128, 1);
    // launches 2..7: projections -> slots 12..23 (launch 5 = ncu capture)
    for (int i = 0; i < 6; i++)
        gemm_k<0><<<gp, blk, SMEM>>>(
            (2 * i) * SL, (2 * i + 1) * SL, WB + 2 * i * M1, WB + (2 * i + 1) * M1,
            0, 0, 0, 0, 1, Bv[i],
            (12 + 2 * i) * SL, (13 + 2 * i) * SL, 0, 1.f, 0, 0, 0);

    // transposes: kr(16,17)->krT(24,25), vr(20,21)->vrT(26,27), vi(22,23)->viT(28,29)
    dim3 gt(32, 32, 16);
    transpose_k<<<gt, 256>>>(16 * SL, 17 * SL, 24 * SL, 25 * SL);
    transpose_k<<<gt, 256>>>(20 * SL, 21 * SL, 26 * SL, 27 * SL);
    transpose_k<<<gt, 256>>>(22 * SL, 23 * SL, 28 * SL, 29 * SL);

    // scores = 0.125*(qr@krT^T + qi@ki^T) -> g_f32[0]
    dim3 gb(8, 8, 16);
    gemm_k<1><<<gb, blk, SMEM>>>(
        12 * SL, 13 * SL, 24 * SL, 25 * SL,
        14 * SL, 15 * SL, 18 * SL, 19 * SL,
        2, nullptr, 0, 0, 0, 0.125f, M1, M1, M1);

    // softmax -> attn (30,31)
    softmax_k<<<16384, 256>>>(30 * SL, 31 * SL);

    // out_r = attn@vrT^T -> g_f32[SL]; out_i = attn@viT^T -> g_f32[2SL]
    gemm_k<1><<<gb, blk, SMEM>>>(
        30 * SL, 31 * SL, 26 * SL, 27 * SL,
        0, 0, 0, 0, 1, nullptr, 0, 0, SL, 1.f, M1, M1, M1);
    gemm_k<1><<<gb, blk, SMEM>>>(
        30 * SL, 31 * SL, 28 * SL, 29 * SL,
        0, 0, 0, 0, 1, nullptr, 0, 0, 2 * SL, 1.f, M1, M1, M1);

    // complex layernorm -> d_out
    complex_ln_k<<<16384, 256>>>(SL, 2 * SL, a2, b2, out);
}